// round 6
// baseline (speedup 1.0000x reference)
#include <cuda_runtime.h>
#include <cstdint>
#include <math.h>

// Problem constants
#define BB   4
#define SS_  1024
#define DD   1024
#define HH_  16
#define DK_  64
#define DFF_ 4096
#define TOK  (BB*SS_)          // 4096 tokens

// ---------------------------------------------------------------------------
// Scratch (static __device__ arrays — the sanctioned no-alloc mechanism)
// ---------------------------------------------------------------------------
__device__ float g_nx  [TOK*DD];
__device__ float g_q   [TOK*DD];
__device__ float g_k   [TOK*DD];
__device__ float g_v   [TOK*DD];
__device__ float g_scores[64*1024*1024];   // [B*H][S][S]  256 MB
__device__ float g_ctx [TOK*DD];
__device__ float g_x1  [TOK*DD];
__device__ float g_nx2r[TOK*DD];
__device__ float g_nx2e[TOK*DD];
__device__ float g_ff  [TOK*DFF_];
__device__ float g_y   [TOK*DD];
__device__ float g_lny [TOK*DD];
// pre-rounded tf32 weights
__device__ float g_wqr [DD*DD];
__device__ float g_wkr [DD*DD];
__device__ float g_wvr [DD*DD];
__device__ float g_wor [DD*DD];
__device__ float g_w1r [DD*DFF_];
__device__ float g_w2r [DFF_*DD];
__device__ float g_w3r [DD*DD];

#define DEVI __device__ __forceinline__

DEVI float f2tf32(float x) {
    uint32_t u;
    asm("cvt.rna.tf32.f32 %0, %1;" : "=r"(u) : "f"(x));
    return __uint_as_float(u);
}
DEVI float gelu_exact(float x) {
    return 0.5f * x * (1.0f + erff(x * 0.70710678118654752f));
}
DEVI void cp_async16(uint32_t dst, const void* src, bool pred) {
    int sz = pred ? 16 : 0;
    asm volatile("cp.async.cg.shared.global [%0], [%1], 16, %2;\n"
                 :: "r"(dst), "l"(src), "r"(sz));
}
DEVI void cp_commit() { asm volatile("cp.async.commit_group;\n"); }
DEVI void cp_wait1()  { asm volatile("cp.async.wait_group 1;\n"); }

DEVI void mma_tf32(float (&c)[4], float a0, float a1, float a2, float a3,
                   float b0, float b1) {
    asm volatile(
        "mma.sync.aligned.m16n8k8.row.col.f32.tf32.tf32.f32 "
        "{%0,%1,%2,%3}, {%4,%5,%6,%7}, {%8,%9}, {%0,%1,%2,%3};"
        : "+f"(c[0]), "+f"(c[1]), "+f"(c[2]), "+f"(c[3])
        : "r"(__float_as_uint(a0)), "r"(__float_as_uint(a1)),
          "r"(__float_as_uint(a2)), "r"(__float_as_uint(a3)),
          "r"(__float_as_uint(b0)), "r"(__float_as_uint(b1)));
}

enum { EPI_NONE = 0, EPI_BIAS = 1, EPI_BIAS_GELU = 2, EPI_BIAS_RES = 3,
       EPI_BIAS_RES2 = 4, EPI_ATTN = 5 };

// ---------------------------------------------------------------------------
// Pipelined tf32 GEMM, tile 128x128x32, 256 threads, warp tile 64x32.
// cp.async double-buffered staging. Inputs must ALREADY be tf32-rounded
// (weights via round_copy, activations via producer epilogues).
// k-slot permutation: mma k-slot c maps to physical k = kk + 2*(c&3)+(c>>2),
// so A fragments load as LDS.64 pairs; B uses the matching physical k rows.
//
// SMEM layout (floats): A[2][4][128][8] at 0 (2x4096), B[2][32][132] at 8192.
// Total 16640 floats = 66560 bytes (dynamic).
// ---------------------------------------------------------------------------
template <int EPI, bool BTRANS, bool ROUND>
__global__ __launch_bounds__(256, 2)
void gemm_tf32_kernel(const float* __restrict__ A, int lda, long long sA1, long long sA2,
                      const float* __restrict__ B, int ldb, long long sB1, long long sB2,
                      float* __restrict__ C, int ldc, long long sC1, long long sC2,
                      int M, int N, int K, int HHd,
                      const float* __restrict__ bias,
                      const float* __restrict__ res1,
                      const float* __restrict__ res2)
{
    extern __shared__ float smem[];
    const uint32_t smem_u = (uint32_t)__cvta_generic_to_shared(smem);

    const int z  = blockIdx.z;
    const int b1 = z / HHd;
    const int b2 = z % HHd;
    A += (size_t)((long long)b1 * sA1 + (long long)b2 * sA2);
    B += (size_t)((long long)b1 * sB1 + (long long)b2 * sB2);
    const size_t coff = (size_t)((long long)b1 * sC1 + (long long)b2 * sC2);

    const int tid  = threadIdx.x;
    const int warp = tid >> 5;
    const int lane = tid & 31;
    const int wm = (warp >> 2) * 64;   // 2 m-groups of 64
    const int wn = (warp & 3) * 32;    // 4 n-groups of 32
    const int r  = lane >> 2;
    const int cq = lane & 3;

    const int blockM = blockIdx.y * 128;
    const int blockN = blockIdx.x * 128;

    float acc[4][4][4];
#pragma unroll
    for (int mt = 0; mt < 4; mt++)
#pragma unroll
        for (int nt = 0; nt < 4; nt++)
#pragma unroll
            for (int i = 0; i < 4; i++) acc[mt][nt][i] = 0.0f;

    // staging: one 32-deep k-tile into buffer bsel
    auto stage = [&](int t, int bsel) {
        const int k0 = t << 5;
        const uint32_t abase = smem_u + (uint32_t)(bsel * 4096) * 4u;
        // A tile 128x32: layout [kkgrp 4][row 128][kin 8]
#pragma unroll
        for (int i = 0; i < 4; i++) {
            int idx = tid + i * 256;
            int row = idx >> 3;
            int c4  = (idx & 7) * 4;
            int gr  = blockM + row;
            bool ok = (gr < M);
            const float* src = A + (ok ? ((size_t)gr * lda + (k0 + c4)) : 0);
            uint32_t dst = abase + (uint32_t)((((c4 >> 3) * 128 + row) * 8 + (c4 & 7)) * 4);
            cp_async16(dst, src, ok);
        }
        if (!BTRANS) {
            const uint32_t bbase = smem_u + (uint32_t)((8192 + bsel * 4224) * 4);
#pragma unroll
            for (int i = 0; i < 4; i++) {
                int idx = tid + i * 256;
                int kr  = idx >> 5;
                int c4  = (idx & 31) * 4;
                int gc  = blockN + c4;
                bool ok = (gc < N);
                const float* src = B + (ok ? ((size_t)(k0 + kr) * ldb + gc) : 0);
                uint32_t dst = bbase + (uint32_t)((kr * 132 + c4) * 4);
                cp_async16(dst, src, ok);
            }
        } else {
            float* Bsh = smem + 8192 + bsel * 4224;
#pragma unroll
            for (int i = 0; i < 4; i++) {
                int idx = tid + i * 256;
                int nr  = idx >> 3;
                int c4  = (idx & 7) * 4;
                int gc  = blockN + nr;
                float4 vv = make_float4(0.f, 0.f, 0.f, 0.f);
                if (gc < N)
                    vv = *(const float4*)(B + (size_t)gc * ldb + (k0 + c4));
                Bsh[(c4 + 0) * 132 + nr] = vv.x;
                Bsh[(c4 + 1) * 132 + nr] = vv.y;
                Bsh[(c4 + 2) * 132 + nr] = vv.z;
                Bsh[(c4 + 3) * 132 + nr] = vv.w;
            }
        }
    };

    const int T = K >> 5;
    stage(0, 0);
    cp_commit();

    for (int t = 0; t < T; t++) {
        const int cur = t & 1;
        if (t + 1 < T) stage(t + 1, cur ^ 1);
        cp_commit();
        cp_wait1();
        __syncthreads();

        const float* Ab = smem + cur * 4096;
        const float* Bb = smem + 8192 + cur * 4224;
#pragma unroll
        for (int kkg = 0; kkg < 4; kkg++) {
            float2 av[4][2];
#pragma unroll
            for (int mt = 0; mt < 4; mt++) {
                int row = wm + mt * 16 + r;
                av[mt][0] = *(const float2*)(Ab + (kkg * 128 + row    ) * 8 + 2 * cq);
                av[mt][1] = *(const float2*)(Ab + (kkg * 128 + row + 8) * 8 + 2 * cq);
            }
#pragma unroll
            for (int nt = 0; nt < 4; nt++) {
                int col = wn + nt * 8 + r;
                float b0 = Bb[(kkg * 8 + 2 * cq    ) * 132 + col];
                float b1 = Bb[(kkg * 8 + 2 * cq + 1) * 132 + col];
#pragma unroll
                for (int mt = 0; mt < 4; mt++)
                    mma_tf32(acc[mt][nt], av[mt][0].x, av[mt][1].x,
                             av[mt][0].y, av[mt][1].y, b0, b1);
            }
        }
        __syncthreads();
    }

    // ---- epilogue + store ----
    float* Cb = C + coff;
#pragma unroll
    for (int mt = 0; mt < 4; mt++) {
#pragma unroll
        for (int nt = 0; nt < 4; nt++) {
#pragma unroll
            for (int rh = 0; rh < 2; rh++) {
                int grow = blockM + wm + mt * 16 + r + rh * 8;
                int gcol = blockN + wn + nt * 8 + cq * 2;
                if (grow < M && gcol < N) {
                    float v0 = acc[mt][nt][rh * 2 + 0];
                    float v1 = acc[mt][nt][rh * 2 + 1];
                    size_t cidx = (size_t)grow * ldc + gcol;
                    if (EPI == EPI_ATTN) {
                        int d0 = gcol     - grow + 63; d0 = min(max(d0, 0), 126);
                        int d1 = gcol + 1 - grow + 63; d1 = min(max(d1, 0), 126);
                        v0 = v0 * 0.125f + bias[d0 * HH_ + b2];
                        v1 = v1 * 0.125f + bias[d1 * HH_ + b2];
                    } else if (EPI != EPI_NONE) {
                        v0 += bias[gcol];
                        v1 += bias[gcol + 1];
                    }
                    if (EPI == EPI_BIAS_GELU) { v0 = gelu_exact(v0); v1 = gelu_exact(v1); }
                    if (EPI == EPI_BIAS_RES || EPI == EPI_BIAS_RES2) {
                        v0 += res1[cidx]; v1 += res1[cidx + 1];
                    }
                    if (EPI == EPI_BIAS_RES2) {
                        v0 += res2[cidx]; v1 += res2[cidx + 1];
                    }
                    if (ROUND) { v0 = f2tf32(v0); v1 = f2tf32(v1); }
                    *(float2*)(Cb + cidx) = make_float2(v0, v1);
                }
            }
        }
    }
}

// ---------------------------------------------------------------------------
// Round-convert fp32 -> tf32(RNA) elementwise (for weights)
// ---------------------------------------------------------------------------
__global__ void round_copy_kernel(const float* __restrict__ s, float* __restrict__ d, int n4)
{
    int i = blockIdx.x * blockDim.x + threadIdx.x;
    if (i < n4) {
        float4 v = ((const float4*)s)[i];
        ((float4*)d)[i] = make_float4(f2tf32(v.x), f2tf32(v.y), f2tf32(v.z), f2tf32(v.w));
    }
}

// ---------------------------------------------------------------------------
// LayerNorm: one 1024-wide row per block of 256 threads.
// Writes tf32-rounded output; if DUAL also the exact fp32 output.
// ---------------------------------------------------------------------------
template <bool DUAL>
__global__ void ln_kernel(const float* __restrict__ x, const float* __restrict__ g,
                          const float* __restrict__ b,
                          float* __restrict__ out_r, float* __restrict__ out_e)
{
    __shared__ float sb[8];
    const int row = blockIdx.x;
    const int t   = threadIdx.x;
    float4 v = ((const float4*)(x + (size_t)row * DD))[t];

    float s = v.x + v.y + v.z + v.w;
#pragma unroll
    for (int o = 16; o; o >>= 1) s += __shfl_xor_sync(0xffffffffu, s, o);
    if ((t & 31) == 0) sb[t >> 5] = s;
    __syncthreads();
    float mean = (sb[0]+sb[1]+sb[2]+sb[3]+sb[4]+sb[5]+sb[6]+sb[7]) * (1.0f / DD);
    __syncthreads();

    float d0 = v.x - mean, d1 = v.y - mean, d2 = v.z - mean, d3 = v.w - mean;
    float s2 = d0*d0 + d1*d1 + d2*d2 + d3*d3;
#pragma unroll
    for (int o = 16; o; o >>= 1) s2 += __shfl_xor_sync(0xffffffffu, s2, o);
    if ((t & 31) == 0) sb[t >> 5] = s2;
    __syncthreads();
    float var = (sb[0]+sb[1]+sb[2]+sb[3]+sb[4]+sb[5]+sb[6]+sb[7]) * (1.0f / DD);
    float inv = rsqrtf(var + 1e-5f);

    float4 gv = ((const float4*)g)[t];
    float4 bv = ((const float4*)b)[t];
    float4 o4 = make_float4(d0 * inv * gv.x + bv.x, d1 * inv * gv.y + bv.y,
                            d2 * inv * gv.z + bv.z, d3 * inv * gv.w + bv.w);
    if (DUAL)
        ((float4*)(out_e + (size_t)row * DD))[t] = o4;
    ((float4*)(out_r + (size_t)row * DD))[t] =
        make_float4(f2tf32(o4.x), f2tf32(o4.y), f2tf32(o4.z), f2tf32(o4.w));
}

// ---------------------------------------------------------------------------
// Row softmax over 1024 elems, in place; output tf32-rounded (feeds P@V GEMM).
// ---------------------------------------------------------------------------
__global__ void softmax_kernel(float* __restrict__ scores)
{
    __shared__ float sb[8];
    const size_t row = blockIdx.x;
    const int t = threadIdx.x;
    float4* p = (float4*)(scores + row * 1024);
    float4 v = p[t];

    float m = fmaxf(fmaxf(v.x, v.y), fmaxf(v.z, v.w));
#pragma unroll
    for (int o = 16; o; o >>= 1) m = fmaxf(m, __shfl_xor_sync(0xffffffffu, m, o));
    if ((t & 31) == 0) sb[t >> 5] = m;
    __syncthreads();
    m = fmaxf(fmaxf(fmaxf(sb[0], sb[1]), fmaxf(sb[2], sb[3])),
              fmaxf(fmaxf(sb[4], sb[5]), fmaxf(sb[6], sb[7])));
    __syncthreads();

    float e0 = __expf(v.x - m), e1 = __expf(v.y - m);
    float e2 = __expf(v.z - m), e3 = __expf(v.w - m);
    float s = e0 + e1 + e2 + e3;
#pragma unroll
    for (int o = 16; o; o >>= 1) s += __shfl_xor_sync(0xffffffffu, s, o);
    if ((t & 31) == 0) sb[t >> 5] = s;
    __syncthreads();
    float tot = sb[0]+sb[1]+sb[2]+sb[3]+sb[4]+sb[5]+sb[6]+sb[7];
    float inv = 1.0f / tot;
    p[t] = make_float4(f2tf32(e0 * inv), f2tf32(e1 * inv),
                       f2tf32(e2 * inv), f2tf32(e3 * inv));
}

// ---------------------------------------------------------------------------
// Launch
// ---------------------------------------------------------------------------
#define GEMM_SMEM 66560

extern "C" void kernel_launch(void* const* d_in, const int* in_sizes, int n_in,
                              void* d_out, int out_size)
{
    (void)in_sizes; (void)n_in; (void)out_size;
    const float* x    = (const float*)d_in[0];
    const float* wq   = (const float*)d_in[1];
    const float* bq   = (const float*)d_in[2];
    const float* wk   = (const float*)d_in[3];
    const float* bk   = (const float*)d_in[4];
    const float* wv   = (const float*)d_in[5];
    const float* bv   = (const float*)d_in[6];
    const float* wo   = (const float*)d_in[7];
    const float* bo   = (const float*)d_in[8];
    const float* relt = (const float*)d_in[9];
    const float* g1   = (const float*)d_in[10];
    const float* be1  = (const float*)d_in[11];
    const float* g2   = (const float*)d_in[12];
    const float* be2  = (const float*)d_in[13];
    const float* w1   = (const float*)d_in[14];
    const float* b1   = (const float*)d_in[15];
    const float* w2   = (const float*)d_in[16];
    const float* b2   = (const float*)d_in[17];
    const float* w3   = (const float*)d_in[18];
    const float* b3   = (const float*)d_in[19];
    const float* gf   = (const float*)d_in[20];
    const float* bf   = (const float*)d_in[21];
    float* out = (float*)d_out;

    float *nx, *q, *k, *v, *sc, *ctx, *x1, *nx2r, *nx2e, *ff, *y, *lny;
    float *wqr, *wkr, *wvr, *wor, *w1r, *w2r, *w3r;
    cudaGetSymbolAddress((void**)&nx,   g_nx);
    cudaGetSymbolAddress((void**)&q,    g_q);
    cudaGetSymbolAddress((void**)&k,    g_k);
    cudaGetSymbolAddress((void**)&v,    g_v);
    cudaGetSymbolAddress((void**)&sc,   g_scores);
    cudaGetSymbolAddress((void**)&ctx,  g_ctx);
    cudaGetSymbolAddress((void**)&x1,   g_x1);
    cudaGetSymbolAddress((void**)&nx2r, g_nx2r);
    cudaGetSymbolAddress((void**)&nx2e, g_nx2e);
    cudaGetSymbolAddress((void**)&ff,   g_ff);
    cudaGetSymbolAddress((void**)&y,    g_y);
    cudaGetSymbolAddress((void**)&lny,  g_lny);
    cudaGetSymbolAddress((void**)&wqr,  g_wqr);
    cudaGetSymbolAddress((void**)&wkr,  g_wkr);
    cudaGetSymbolAddress((void**)&wvr,  g_wvr);
    cudaGetSymbolAddress((void**)&wor,  g_wor);
    cudaGetSymbolAddress((void**)&w1r,  g_w1r);
    cudaGetSymbolAddress((void**)&w2r,  g_w2r);
    cudaGetSymbolAddress((void**)&w3r,  g_w3r);

    // opt-in dynamic smem for every instantiation used
    cudaFuncSetAttribute(gemm_tf32_kernel<EPI_BIAS,      false, true >, cudaFuncAttributeMaxDynamicSharedMemorySize, GEMM_SMEM);
    cudaFuncSetAttribute(gemm_tf32_kernel<EPI_ATTN,      true,  false>, cudaFuncAttributeMaxDynamicSharedMemorySize, GEMM_SMEM);
    cudaFuncSetAttribute(gemm_tf32_kernel<EPI_NONE,      false, true >, cudaFuncAttributeMaxDynamicSharedMemorySize, GEMM_SMEM);
    cudaFuncSetAttribute(gemm_tf32_kernel<EPI_BIAS_RES,  false, false>, cudaFuncAttributeMaxDynamicSharedMemorySize, GEMM_SMEM);
    cudaFuncSetAttribute(gemm_tf32_kernel<EPI_BIAS_GELU, false, true >, cudaFuncAttributeMaxDynamicSharedMemorySize, GEMM_SMEM);
    cudaFuncSetAttribute(gemm_tf32_kernel<EPI_BIAS_RES2, false, false>, cudaFuncAttributeMaxDynamicSharedMemorySize, GEMM_SMEM);

    const long long SD = (long long)SS_ * DD;       // 1,048,576
    const long long S2 = (long long)SS_ * SS_;      // 1,048,576

    // 0. round weights to tf32 once per launch
    round_copy_kernel<<<(DD*DD/4 + 255)/256, 256>>>(wq, wqr, DD*DD/4);
    round_copy_kernel<<<(DD*DD/4 + 255)/256, 256>>>(wk, wkr, DD*DD/4);
    round_copy_kernel<<<(DD*DD/4 + 255)/256, 256>>>(wv, wvr, DD*DD/4);
    round_copy_kernel<<<(DD*DD/4 + 255)/256, 256>>>(wo, wor, DD*DD/4);
    round_copy_kernel<<<(DD*DFF_/4 + 255)/256, 256>>>(w1, w1r, DD*DFF_/4);
    round_copy_kernel<<<(DFF_*DD/4 + 255)/256, 256>>>(w2, w2r, DFF_*DD/4);
    round_copy_kernel<<<(DD*DD/4 + 255)/256, 256>>>(w3, w3r, DD*DD/4);

    // 1. nx = round(LN(x, g1, be1))
    ln_kernel<false><<<TOK, 256>>>(x, g1, be1, nx, nullptr);

    // 2-4. Q/K/V = round(nx @ w + b)
    gemm_tf32_kernel<EPI_BIAS, false, true><<<dim3(8, 32, 1), 256, GEMM_SMEM>>>(
        nx, DD, 0, 0, wqr, DD, 0, 0, q, DD, 0, 0, TOK, DD, DD, 1, bq, nullptr, nullptr);
    gemm_tf32_kernel<EPI_BIAS, false, true><<<dim3(8, 32, 1), 256, GEMM_SMEM>>>(
        nx, DD, 0, 0, wkr, DD, 0, 0, k, DD, 0, 0, TOK, DD, DD, 1, bk, nullptr, nullptr);
    gemm_tf32_kernel<EPI_BIAS, false, true><<<dim3(8, 32, 1), 256, GEMM_SMEM>>>(
        nx, DD, 0, 0, wvr, DD, 0, 0, v, DD, 0, 0, TOK, DD, DD, 1, bv, nullptr, nullptr);

    // 5. scores[bh] = Q_bh @ K_bh^T / 8 + rel_bias
    gemm_tf32_kernel<EPI_ATTN, true, false><<<dim3(8, 8, BB * HH_), 256, GEMM_SMEM>>>(
        q, DD, SD, DK_, k, DD, SD, DK_, sc, SS_, (long long)HH_ * S2, S2,
        SS_, SS_, DK_, HH_, relt, nullptr, nullptr);

    // 6. softmax rows (rounded output)
    softmax_kernel<<<BB * HH_ * SS_, 256>>>(sc);

    // 7. ctx[bh] = round(P @ V_bh)
    gemm_tf32_kernel<EPI_NONE, false, true><<<dim3(1, 8, BB * HH_), 256, GEMM_SMEM>>>(
        sc, SS_, (long long)HH_ * S2, S2, v, DD, SD, DK_, ctx, DD, SD, DK_,
        SS_, DK_, SS_, HH_, nullptr, nullptr, nullptr);

    // 8. x1 = x + ctx @ wo + bo
    gemm_tf32_kernel<EPI_BIAS_RES, false, false><<<dim3(8, 32, 1), 256, GEMM_SMEM>>>(
        ctx, DD, 0, 0, wor, DD, 0, 0, x1, DD, 0, 0, TOK, DD, DD, 1, bo, x, nullptr);

    // 9. nx2 = LN(x1)  (exact + rounded)
    ln_kernel<true><<<TOK, 256>>>(x1, g2, be2, nx2r, nx2e);

    // 10. ff = round(gelu(nx2 @ w1 + b1))
    gemm_tf32_kernel<EPI_BIAS_GELU, false, true><<<dim3(32, 32, 1), 256, GEMM_SMEM>>>(
        nx2r, DD, 0, 0, w1r, DFF_, 0, 0, ff, DFF_, 0, 0, TOK, DFF_, DD, 1, b1, nullptr, nullptr);

    // 11. y = nx2 + ff @ w2 + b2
    gemm_tf32_kernel<EPI_BIAS_RES, false, false><<<dim3(8, 32, 1), 256, GEMM_SMEM>>>(
        ff, DFF_, 0, 0, w2r, DD, 0, 0, y, DD, 0, 0, TOK, DD, DFF_, 1, b2, nx2e, nullptr);

    // 12. lny = round(LN(y))
    ln_kernel<false><<<TOK, 256>>>(y, gf, bf, lny, nullptr);

    // 13. out = x1 + y + lny @ w3 + b3
    gemm_tf32_kernel<EPI_BIAS_RES2, false, false><<<dim3(8, 32, 1), 256, GEMM_SMEM>>>(
        lny, DD, 0, 0, w3r, DD, 0, 0, out, DD, 0, 0, TOK, DD, DD, 1, b3, y, x1);
}

// round 7
// speedup vs baseline: 1.1772x; 1.1772x over previous
#include <cuda_runtime.h>
#include <cstdint>
#include <math.h>

// Problem constants
#define BB   4
#define SS_  1024
#define DD   1024
#define HH_  16
#define DK_  64
#define DFF_ 4096
#define TOK  (BB*SS_)          // 4096 tokens

// ---------------------------------------------------------------------------
// Scratch (static __device__ arrays — the sanctioned no-alloc mechanism)
// ---------------------------------------------------------------------------
__device__ float g_nx  [TOK*DD];
__device__ float g_q   [TOK*DD];
__device__ float g_k   [TOK*DD];
__device__ float g_v   [TOK*DD];
__device__ float g_ctx [TOK*DD];
__device__ float g_x1  [TOK*DD];
__device__ float g_nx2r[TOK*DD];
__device__ float g_nx2e[TOK*DD];
__device__ float g_ff  [TOK*DFF_];
__device__ float g_y   [TOK*DD];
__device__ float g_lny [TOK*DD];

#define DEVI __device__ __forceinline__

DEVI float f2tf32(float x) {
    uint32_t u;
    asm("cvt.rna.tf32.f32 %0, %1;" : "=r"(u) : "f"(x));
    return __uint_as_float(u);
}
DEVI float gelu_exact(float x) {
    return 0.5f * x * (1.0f + erff(x * 0.70710678118654752f));
}
DEVI void cp_async16(uint32_t dst, const void* src, bool pred) {
    int sz = pred ? 16 : 0;
    asm volatile("cp.async.cg.shared.global [%0], [%1], 16, %2;\n"
                 :: "r"(dst), "l"(src), "r"(sz));
}
DEVI void cp_commit() { asm volatile("cp.async.commit_group;\n"); }
DEVI void cp_wait1()  { asm volatile("cp.async.wait_group 1;\n"); }

DEVI void mma_tf32(float (&c)[4], float a0, float a1, float a2, float a3,
                   float b0, float b1) {
    asm volatile(
        "mma.sync.aligned.m16n8k8.row.col.f32.tf32.tf32.f32 "
        "{%0,%1,%2,%3}, {%4,%5,%6,%7}, {%8,%9}, {%0,%1,%2,%3};"
        : "+f"(c[0]), "+f"(c[1]), "+f"(c[2]), "+f"(c[3])
        : "r"(__float_as_uint(a0)), "r"(__float_as_uint(a1)),
          "r"(__float_as_uint(a2)), "r"(__float_as_uint(a3)),
          "r"(__float_as_uint(b0)), "r"(__float_as_uint(b1)));
}

enum { EPI_NONE = 0, EPI_BIAS = 1, EPI_BIAS_GELU = 2, EPI_BIAS_RES = 3,
       EPI_BIAS_RES2 = 4 };

// ---------------------------------------------------------------------------
// Pipelined tf32 GEMM, tile 128x128x32, 256 threads, warp tile 64x32.
// cp.async double-buffered staging. A activations are pre-rounded tf32;
// B (weights) are raw fp32 — mma truncation handles them.
// SMEM (floats): A[2][4][128][8] at 0, B[2][32][132] at 8192. 66560 bytes.
// ---------------------------------------------------------------------------
template <int EPI, bool ROUND>
__global__ __launch_bounds__(256, 2)
void gemm_tf32_kernel(const float* __restrict__ A, int lda,
                      const float* __restrict__ B, int ldb,
                      float* __restrict__ C, int ldc,
                      int M, int N, int K,
                      const float* __restrict__ bias,
                      const float* __restrict__ res1,
                      const float* __restrict__ res2)
{
    extern __shared__ float smem[];
    const uint32_t smem_u = (uint32_t)__cvta_generic_to_shared(smem);

    const int tid  = threadIdx.x;
    const int warp = tid >> 5;
    const int lane = tid & 31;
    const int wm = (warp >> 2) * 64;
    const int wn = (warp & 3) * 32;
    const int r  = lane >> 2;
    const int cq = lane & 3;

    const int blockM = blockIdx.y * 128;
    const int blockN = blockIdx.x * 128;

    float acc[4][4][4];
#pragma unroll
    for (int mt = 0; mt < 4; mt++)
#pragma unroll
        for (int nt = 0; nt < 4; nt++)
#pragma unroll
            for (int i = 0; i < 4; i++) acc[mt][nt][i] = 0.0f;

    auto stage = [&](int t, int bsel) {
        const int k0 = t << 5;
        const uint32_t abase = smem_u + (uint32_t)(bsel * 4096) * 4u;
#pragma unroll
        for (int i = 0; i < 4; i++) {
            int idx = tid + i * 256;
            int row = idx >> 3;
            int c4  = (idx & 7) * 4;
            int gr  = blockM + row;
            bool ok = (gr < M);
            const float* src = A + (ok ? ((size_t)gr * lda + (k0 + c4)) : 0);
            uint32_t dst = abase + (uint32_t)((((c4 >> 3) * 128 + row) * 8 + (c4 & 7)) * 4);
            cp_async16(dst, src, ok);
        }
        const uint32_t bbase = smem_u + (uint32_t)((8192 + bsel * 4224) * 4);
#pragma unroll
        for (int i = 0; i < 4; i++) {
            int idx = tid + i * 256;
            int kr  = idx >> 5;
            int c4  = (idx & 31) * 4;
            int gc  = blockN + c4;
            bool ok = (gc < N);
            const float* src = B + (ok ? ((size_t)(k0 + kr) * ldb + gc) : 0);
            uint32_t dst = bbase + (uint32_t)((kr * 132 + c4) * 4);
            cp_async16(dst, src, ok);
        }
    };

    const int T = K >> 5;
    stage(0, 0);
    cp_commit();

    for (int t = 0; t < T; t++) {
        const int cur = t & 1;
        if (t + 1 < T) stage(t + 1, cur ^ 1);
        cp_commit();
        cp_wait1();
        __syncthreads();

        const float* Ab = smem + cur * 4096;
        const float* Bb = smem + 8192 + cur * 4224;
#pragma unroll
        for (int kkg = 0; kkg < 4; kkg++) {
            float2 av[4][2];
#pragma unroll
            for (int mt = 0; mt < 4; mt++) {
                int row = wm + mt * 16 + r;
                av[mt][0] = *(const float2*)(Ab + (kkg * 128 + row    ) * 8 + 2 * cq);
                av[mt][1] = *(const float2*)(Ab + (kkg * 128 + row + 8) * 8 + 2 * cq);
            }
#pragma unroll
            for (int nt = 0; nt < 4; nt++) {
                int col = wn + nt * 8 + r;
                float b0 = Bb[(kkg * 8 + 2 * cq    ) * 132 + col];
                float b1 = Bb[(kkg * 8 + 2 * cq + 1) * 132 + col];
#pragma unroll
                for (int mt = 0; mt < 4; mt++)
                    mma_tf32(acc[mt][nt], av[mt][0].x, av[mt][1].x,
                             av[mt][0].y, av[mt][1].y, b0, b1);
            }
        }
        __syncthreads();
    }

    // ---- epilogue + store ----
#pragma unroll
    for (int mt = 0; mt < 4; mt++) {
#pragma unroll
        for (int nt = 0; nt < 4; nt++) {
#pragma unroll
            for (int rh = 0; rh < 2; rh++) {
                int grow = blockM + wm + mt * 16 + r + rh * 8;
                int gcol = blockN + wn + nt * 8 + cq * 2;
                if (grow < M && gcol < N) {
                    float v0 = acc[mt][nt][rh * 2 + 0];
                    float v1 = acc[mt][nt][rh * 2 + 1];
                    size_t cidx = (size_t)grow * ldc + gcol;
                    if (EPI != EPI_NONE) {
                        v0 += bias[gcol];
                        v1 += bias[gcol + 1];
                    }
                    if (EPI == EPI_BIAS_GELU) { v0 = gelu_exact(v0); v1 = gelu_exact(v1); }
                    if (EPI == EPI_BIAS_RES || EPI == EPI_BIAS_RES2) {
                        v0 += res1[cidx]; v1 += res1[cidx + 1];
                    }
                    if (EPI == EPI_BIAS_RES2) {
                        v0 += res2[cidx]; v1 += res2[cidx + 1];
                    }
                    if (ROUND) { v0 = f2tf32(v0); v1 = f2tf32(v1); }
                    *(float2*)(C + cidx) = make_float2(v0, v1);
                }
            }
        }
    }
}

// ---------------------------------------------------------------------------
// Fused flash attention. Grid (8 q-tiles, B*H). 256 threads = 8 warps.
// Q tile 128x64 (warp w owns rows 16w..16w+15), K/V tiles 64x64 streamed via
// cp.async double-buffer. Online softmax on mma fragments; P re-fragmented
// through warp-private SMEM for the P@V mma.
// SMEM floats: K[2] @ {0,4352}, V[2] @ {8704,13056}, P[w] @ 17408+w*1152,
// bias @ 26624 (128). Total 26752 floats = 107008 bytes.
// ---------------------------------------------------------------------------
#define FA_SMEM 107008

__global__ __launch_bounds__(256, 1)
void flash_attn_kernel(const float* __restrict__ Q, const float* __restrict__ K,
                       const float* __restrict__ V, const float* __restrict__ relt,
                       float* __restrict__ ctx)
{
    extern __shared__ float sm[];
    const uint32_t sm_u = (uint32_t)__cvta_generic_to_shared(sm);

    const int tid  = threadIdx.x;
    const int warp = tid >> 5;
    const int lane = tid & 31;
    const int r  = lane >> 2;
    const int cq = lane & 3;
    const int qt = blockIdx.x;
    const int bh = blockIdx.y;
    const int b  = bh >> 4, h = bh & 15;

    const size_t base = (size_t)b * SS_ * DD + (size_t)h * DK_;
    const int qrow = qt * 128 + warp * 16 + r;           // rows qrow, qrow+8

    if (tid < 127) sm[26624 + tid] = relt[tid * HH_ + h];

    // Q fragments (scaled by 1/sqrt(64) = 0.125), kept in registers
    const float* qp  = Q + base + (size_t)qrow * DD;
    const float* qp8 = qp + (size_t)8 * DD;
    float2 qa[8][2];
#pragma unroll
    for (int kk = 0; kk < 8; kk++) {
        float2 v0 = *(const float2*)(qp  + kk * 8 + 2 * cq);
        float2 v1 = *(const float2*)(qp8 + kk * 8 + 2 * cq);
        qa[kk][0] = make_float2(v0.x * 0.125f, v0.y * 0.125f);
        qa[kk][1] = make_float2(v1.x * 0.125f, v1.y * 0.125f);
    }

    auto stage = [&](int j, int bsel) {
#pragma unroll
        for (int i = 0; i < 4; i++) {
            int idx = tid + i * 256;
            int t   = idx >> 4;            // 0..63
            int sg  = (idx & 15) * 4;      // 0..60
            const float* kr_ = K + base + (size_t)(j * 64 + t) * DD + sg;
            const float* vr_ = V + base + (size_t)(j * 64 + t) * DD + sg;
            cp_async16(sm_u + (uint32_t)((bsel * 4352 + t * 68 + sg) * 4), kr_, true);
            cp_async16(sm_u + (uint32_t)(((8704 + bsel * 4352) + t * 68 + sg) * 4), vr_, true);
        }
    };

    float oacc[8][4];
#pragma unroll
    for (int nf = 0; nf < 8; nf++)
#pragma unroll
        for (int i = 0; i < 4; i++) oacc[nf][i] = 0.0f;
    float m0 = -3e38f, m1 = -3e38f, l0 = 0.0f, l1 = 0.0f;

    stage(0, 0);
    cp_commit();

    float* Pw = sm + 17408 + warp * 1152;
    const float* bias_sm = sm + 26624;

    for (int j = 0; j < 16; j++) {
        const int cur = j & 1;
        if (j + 1 < 16) stage(j + 1, cur ^ 1);
        cp_commit();
        cp_wait1();
        __syncthreads();

        const float* Ks = sm + cur * 4352;
        const float* Vs = sm + 8704 + cur * 4352;

        // ---- S = (Q/8) @ K^T : 16x64 per warp ----
        float s[8][4];
#pragma unroll
        for (int nf = 0; nf < 8; nf++)
            s[nf][0] = s[nf][1] = s[nf][2] = s[nf][3] = 0.0f;
#pragma unroll
        for (int kk = 0; kk < 8; kk++) {
#pragma unroll
            for (int nf = 0; nf < 8; nf++) {
                float2 kb = *(const float2*)(Ks + (nf * 8 + r) * 68 + kk * 8 + 2 * cq);
                mma_tf32(s[nf], qa[kk][0].x, qa[kk][1].x, qa[kk][0].y, qa[kk][1].y,
                         kb.x, kb.y);
            }
        }

        // ---- rel-position bias ----
        const int row0 = qrow, row1 = qrow + 8;
        const int colb = j * 64 + 2 * cq;
#pragma unroll
        for (int nf = 0; nf < 8; nf++) {
            int c0 = colb + nf * 8, c1 = c0 + 1;
            int d00 = min(max(c0 - row0 + 63, 0), 126);
            int d01 = min(max(c1 - row0 + 63, 0), 126);
            int d10 = min(max(c0 - row1 + 63, 0), 126);
            int d11 = min(max(c1 - row1 + 63, 0), 126);
            s[nf][0] += bias_sm[d00];
            s[nf][1] += bias_sm[d01];
            s[nf][2] += bias_sm[d10];
            s[nf][3] += bias_sm[d11];
        }

        // ---- online softmax ----
        float rm0 = -3e38f, rm1 = -3e38f;
#pragma unroll
        for (int nf = 0; nf < 8; nf++) {
            rm0 = fmaxf(rm0, fmaxf(s[nf][0], s[nf][1]));
            rm1 = fmaxf(rm1, fmaxf(s[nf][2], s[nf][3]));
        }
        rm0 = fmaxf(rm0, __shfl_xor_sync(0xffffffffu, rm0, 1));
        rm0 = fmaxf(rm0, __shfl_xor_sync(0xffffffffu, rm0, 2));
        rm1 = fmaxf(rm1, __shfl_xor_sync(0xffffffffu, rm1, 1));
        rm1 = fmaxf(rm1, __shfl_xor_sync(0xffffffffu, rm1, 2));
        float mn0 = fmaxf(m0, rm0), mn1 = fmaxf(m1, rm1);
        float a0 = __expf(m0 - mn0), a1 = __expf(m1 - mn1);
        m0 = mn0; m1 = mn1;
        float sum0 = 0.0f, sum1 = 0.0f;
#pragma unroll
        for (int nf = 0; nf < 8; nf++) {
            s[nf][0] = __expf(s[nf][0] - mn0);
            s[nf][1] = __expf(s[nf][1] - mn0);
            s[nf][2] = __expf(s[nf][2] - mn1);
            s[nf][3] = __expf(s[nf][3] - mn1);
            sum0 += s[nf][0] + s[nf][1];
            sum1 += s[nf][2] + s[nf][3];
        }
        sum0 += __shfl_xor_sync(0xffffffffu, sum0, 1);
        sum0 += __shfl_xor_sync(0xffffffffu, sum0, 2);
        sum1 += __shfl_xor_sync(0xffffffffu, sum1, 1);
        sum1 += __shfl_xor_sync(0xffffffffu, sum1, 2);
        l0 = l0 * a0 + sum0;
        l1 = l1 * a1 + sum1;
#pragma unroll
        for (int nf = 0; nf < 8; nf++) {
            oacc[nf][0] *= a0; oacc[nf][1] *= a0;
            oacc[nf][2] *= a1; oacc[nf][3] *= a1;
        }

        // ---- P through warp-private SMEM (C-frag -> A-frag relayout) ----
#pragma unroll
        for (int nf = 0; nf < 8; nf++) {
            *(float2*)(Pw + r * 72 + nf * 8 + 2 * cq) =
                make_float2(f2tf32(s[nf][0]), f2tf32(s[nf][1]));
            *(float2*)(Pw + (r + 8) * 72 + nf * 8 + 2 * cq) =
                make_float2(f2tf32(s[nf][2]), f2tf32(s[nf][3]));
        }
        __syncwarp();

        // ---- O += P @ V ----
#pragma unroll
        for (int kk = 0; kk < 8; kk++) {
            float2 pa0 = *(const float2*)(Pw + r * 72 + kk * 8 + 2 * cq);
            float2 pa1 = *(const float2*)(Pw + (r + 8) * 72 + kk * 8 + 2 * cq);
#pragma unroll
            for (int nf = 0; nf < 8; nf++) {
                float vb0 = Vs[(kk * 8 + 2 * cq    ) * 68 + nf * 8 + r];
                float vb1 = Vs[(kk * 8 + 2 * cq + 1) * 68 + nf * 8 + r];
                mma_tf32(oacc[nf], pa0.x, pa1.x, pa0.y, pa1.y, vb0, vb1);
            }
        }
        __syncthreads();
    }

    // ---- epilogue: normalize + store ctx (tf32-rounded for O-proj GEMM) ----
    const float inv0 = 1.0f / l0, inv1 = 1.0f / l1;
    float* op  = ctx + base + (size_t)qrow * DD;
    float* op8 = op + (size_t)8 * DD;
#pragma unroll
    for (int nf = 0; nf < 8; nf++) {
        *(float2*)(op + nf * 8 + 2 * cq) =
            make_float2(f2tf32(oacc[nf][0] * inv0), f2tf32(oacc[nf][1] * inv0));
        *(float2*)(op8 + nf * 8 + 2 * cq) =
            make_float2(f2tf32(oacc[nf][2] * inv1), f2tf32(oacc[nf][3] * inv1));
    }
}

// ---------------------------------------------------------------------------
// LayerNorm: one 1024-wide row per block of 256 threads.
// Writes tf32-rounded output; if DUAL also the exact fp32 output.
// ---------------------------------------------------------------------------
template <bool DUAL>
__global__ void ln_kernel(const float* __restrict__ x, const float* __restrict__ g,
                          const float* __restrict__ b,
                          float* __restrict__ out_r, float* __restrict__ out_e)
{
    __shared__ float sb[8];
    const int row = blockIdx.x;
    const int t   = threadIdx.x;
    float4 v = ((const float4*)(x + (size_t)row * DD))[t];

    float s = v.x + v.y + v.z + v.w;
#pragma unroll
    for (int o = 16; o; o >>= 1) s += __shfl_xor_sync(0xffffffffu, s, o);
    if ((t & 31) == 0) sb[t >> 5] = s;
    __syncthreads();
    float mean = (sb[0]+sb[1]+sb[2]+sb[3]+sb[4]+sb[5]+sb[6]+sb[7]) * (1.0f / DD);
    __syncthreads();

    float d0 = v.x - mean, d1 = v.y - mean, d2 = v.z - mean, d3 = v.w - mean;
    float s2 = d0*d0 + d1*d1 + d2*d2 + d3*d3;
#pragma unroll
    for (int o = 16; o; o >>= 1) s2 += __shfl_xor_sync(0xffffffffu, s2, o);
    if ((t & 31) == 0) sb[t >> 5] = s2;
    __syncthreads();
    float var = (sb[0]+sb[1]+sb[2]+sb[3]+sb[4]+sb[5]+sb[6]+sb[7]) * (1.0f / DD);
    float inv = rsqrtf(var + 1e-5f);

    float4 gv = ((const float4*)g)[t];
    float4 bv = ((const float4*)b)[t];
    float4 o4 = make_float4(d0 * inv * gv.x + bv.x, d1 * inv * gv.y + bv.y,
                            d2 * inv * gv.z + bv.z, d3 * inv * gv.w + bv.w);
    if (DUAL)
        ((float4*)(out_e + (size_t)row * DD))[t] = o4;
    ((float4*)(out_r + (size_t)row * DD))[t] =
        make_float4(f2tf32(o4.x), f2tf32(o4.y), f2tf32(o4.z), f2tf32(o4.w));
}

// ---------------------------------------------------------------------------
// Launch
// ---------------------------------------------------------------------------
#define GEMM_SMEM 66560

extern "C" void kernel_launch(void* const* d_in, const int* in_sizes, int n_in,
                              void* d_out, int out_size)
{
    (void)in_sizes; (void)n_in; (void)out_size;
    const float* x    = (const float*)d_in[0];
    const float* wq   = (const float*)d_in[1];
    const float* bq   = (const float*)d_in[2];
    const float* wk   = (const float*)d_in[3];
    const float* bk   = (const float*)d_in[4];
    const float* wv   = (const float*)d_in[5];
    const float* bv   = (const float*)d_in[6];
    const float* wo   = (const float*)d_in[7];
    const float* bo   = (const float*)d_in[8];
    const float* relt = (const float*)d_in[9];
    const float* g1   = (const float*)d_in[10];
    const float* be1  = (const float*)d_in[11];
    const float* g2   = (const float*)d_in[12];
    const float* be2  = (const float*)d_in[13];
    const float* w1   = (const float*)d_in[14];
    const float* b1   = (const float*)d_in[15];
    const float* w2   = (const float*)d_in[16];
    const float* b2   = (const float*)d_in[17];
    const float* w3   = (const float*)d_in[18];
    const float* b3   = (const float*)d_in[19];
    const float* gf   = (const float*)d_in[20];
    const float* bf   = (const float*)d_in[21];
    float* out = (float*)d_out;

    float *nx, *q, *k, *v, *ctx, *x1, *nx2r, *nx2e, *ff, *y, *lny;
    cudaGetSymbolAddress((void**)&nx,   g_nx);
    cudaGetSymbolAddress((void**)&q,    g_q);
    cudaGetSymbolAddress((void**)&k,    g_k);
    cudaGetSymbolAddress((void**)&v,    g_v);
    cudaGetSymbolAddress((void**)&ctx,  g_ctx);
    cudaGetSymbolAddress((void**)&x1,   g_x1);
    cudaGetSymbolAddress((void**)&nx2r, g_nx2r);
    cudaGetSymbolAddress((void**)&nx2e, g_nx2e);
    cudaGetSymbolAddress((void**)&ff,   g_ff);
    cudaGetSymbolAddress((void**)&y,    g_y);
    cudaGetSymbolAddress((void**)&lny,  g_lny);

    cudaFuncSetAttribute(gemm_tf32_kernel<EPI_BIAS,      true >, cudaFuncAttributeMaxDynamicSharedMemorySize, GEMM_SMEM);
    cudaFuncSetAttribute(gemm_tf32_kernel<EPI_BIAS_RES,  false>, cudaFuncAttributeMaxDynamicSharedMemorySize, GEMM_SMEM);
    cudaFuncSetAttribute(gemm_tf32_kernel<EPI_BIAS_GELU, true >, cudaFuncAttributeMaxDynamicSharedMemorySize, GEMM_SMEM);
    cudaFuncSetAttribute(gemm_tf32_kernel<EPI_BIAS_RES2, false>, cudaFuncAttributeMaxDynamicSharedMemorySize, GEMM_SMEM);
    cudaFuncSetAttribute(flash_attn_kernel, cudaFuncAttributeMaxDynamicSharedMemorySize, FA_SMEM);

    // 1. nx = round(LN(x, g1, be1))
    ln_kernel<false><<<TOK, 256>>>(x, g1, be1, nx, nullptr);

    // 2-4. Q/K/V = round(nx @ w + b)
    gemm_tf32_kernel<EPI_BIAS, true><<<dim3(8, 32), 256, GEMM_SMEM>>>(
        nx, DD, wq, DD, q, DD, TOK, DD, DD, bq, nullptr, nullptr);
    gemm_tf32_kernel<EPI_BIAS, true><<<dim3(8, 32), 256, GEMM_SMEM>>>(
        nx, DD, wk, DD, k, DD, TOK, DD, DD, bk, nullptr, nullptr);
    gemm_tf32_kernel<EPI_BIAS, true><<<dim3(8, 32), 256, GEMM_SMEM>>>(
        nx, DD, wv, DD, v, DD, TOK, DD, DD, bv, nullptr, nullptr);

    // 5. fused attention -> ctx
    flash_attn_kernel<<<dim3(8, BB * HH_), 256, FA_SMEM>>>(q, k, v, relt, ctx);

    // 6. x1 = x + ctx @ wo + bo
    gemm_tf32_kernel<EPI_BIAS_RES, false><<<dim3(8, 32), 256, GEMM_SMEM>>>(
        ctx, DD, wo, DD, x1, DD, TOK, DD, DD, bo, x, nullptr);

    // 7. nx2 = LN(x1)  (exact + rounded)
    ln_kernel<true><<<TOK, 256>>>(x1, g2, be2, nx2r, nx2e);

    // 8. ff = round(gelu(nx2 @ w1 + b1))
    gemm_tf32_kernel<EPI_BIAS_GELU, true><<<dim3(32, 32), 256, GEMM_SMEM>>>(
        nx2r, DD, w1, DFF_, ff, DFF_, TOK, DFF_, DD, b1, nullptr, nullptr);

    // 9. y = nx2 + ff @ w2 + b2
    gemm_tf32_kernel<EPI_BIAS_RES, false><<<dim3(8, 32), 256, GEMM_SMEM>>>(
        ff, DFF_, w2, DD, y, DD, TOK, DD, DFF_, b2, nx2e, nullptr);

    // 10. lny = round(LN(y))
    ln_kernel<false><<<TOK, 256>>>(y, gf, bf, lny, nullptr);

    // 11. out = x1 + y + lny @ w3 + b3
    gemm_tf32_kernel<EPI_BIAS_RES2, false><<<dim3(8, 32), 256, GEMM_SMEM>>>(
        lny, DD, w3, DD, out, DD, TOK, DD, DD, b3, y, x1);
}